// round 1
// baseline (speedup 1.0000x reference)
#include <cuda_runtime.h>
#include <cuda_bf16.h>

#define Bsz 512
#define Nn  98
#define DIM 512
#define NH  16
#define HD  32
#define BH  (Bsz*NH)          // 8192
#define Mrows (Bsz*Nn)        // 50176
#define QKV_N (3*DIM)         // 1536
#define SCALE 0.17677669529663687f   // 32^-0.5

// scratch (device globals: allocation-free rule)
__device__ float g_q[BH*Nn*HD];
__device__ float g_k[BH*Nn*HD];
__device__ float g_v[BH*Nn*HD];
__device__ float g_att[Mrows*DIM];

// ---------------------------------------------------------------------------
// Tiled SGEMM 128x128x8, 256 threads, 8x8 micro-tile.
// A: [M,K] row-major, Bmat: [K,N] row-major. M%128==0, N%128==0, K%8==0.
// ---------------------------------------------------------------------------

#define GEMM_BODY(EPILOGUE)                                                    \
    __shared__ float As[8][128];                                               \
    __shared__ float Bs[8][128];                                               \
    const int tid  = threadIdx.x;                                              \
    const int bm   = blockIdx.y * 128;                                         \
    const int bn   = blockIdx.x * 128;                                         \
    const int arow = tid >> 1;                                                 \
    const int acol = (tid & 1) * 4;                                            \
    const int brow = tid >> 5;                                                 \
    const int bcol = (tid & 31) * 4;                                           \
    const int tx   = tid & 15;                                                 \
    const int ty   = tid >> 4;                                                 \
    float acc[8][8];                                                           \
    _Pragma("unroll") for (int i = 0; i < 8; i++)                              \
        _Pragma("unroll") for (int j = 0; j < 8; j++) acc[i][j] = 0.f;         \
    for (int k0 = 0; k0 < K; k0 += 8) {                                        \
        float4 av = *(const float4*)(A + (size_t)(bm + arow) * K + k0 + acol); \
        As[acol + 0][arow] = av.x;                                             \
        As[acol + 1][arow] = av.y;                                             \
        As[acol + 2][arow] = av.z;                                             \
        As[acol + 3][arow] = av.w;                                             \
        *(float4*)&Bs[brow][bcol] =                                            \
            *(const float4*)(Bmat + (size_t)(k0 + brow) * N + bn + bcol);      \
        __syncthreads();                                                       \
        _Pragma("unroll") for (int k = 0; k < 8; k++) {                        \
            float a[8], b[8];                                                  \
            _Pragma("unroll") for (int i = 0; i < 8; i++) a[i] = As[k][ty * 8 + i]; \
            _Pragma("unroll") for (int j = 0; j < 8; j++) b[j] = Bs[k][tx * 8 + j]; \
            _Pragma("unroll") for (int i = 0; i < 8; i++)                      \
                _Pragma("unroll") for (int j = 0; j < 8; j++)                  \
                    acc[i][j] += a[i] * b[j];                                  \
        }                                                                      \
        __syncthreads();                                                       \
    }                                                                          \
    EPILOGUE

// QKV GEMM: epilogue scatters into g_q (scaled), g_k, g_v with [BH, N, HD] layout.
__global__ __launch_bounds__(256) void qkv_gemm_kernel(
    const float* __restrict__ A, const float* __restrict__ Bmat,
    const float* __restrict__ bias)
{
    const int K = DIM, N = QKV_N;
    GEMM_BODY({
        _Pragma("unroll") for (int i = 0; i < 8; i++) {
            const int m = bm + ty * 8 + i;
            const int b = m / Nn;
            const int r = m - b * Nn;
            _Pragma("unroll") for (int j = 0; j < 8; j++) {
                const int n = bn + tx * 8 + j;
                float val = acc[i][j] + bias[n];
                const int which = n >> 9;          // 0:q 1:k 2:v
                const int h  = (n >> 5) & (NH - 1);
                const int hd = n & (HD - 1);
                const int idx = ((b * NH + h) * Nn + r) * HD + hd;
                if (which == 0)      g_q[idx] = val * SCALE;
                else if (which == 1) g_k[idx] = val;
                else                 g_v[idx] = val;
            }
        }
    })
}

// Proj GEMM: reads g_att, writes final output + bias.
__global__ __launch_bounds__(256) void proj_gemm_kernel(
    const float* __restrict__ A, const float* __restrict__ Bmat,
    const float* __restrict__ bias, float* __restrict__ out)
{
    const int K = DIM, N = DIM;
    GEMM_BODY({
        _Pragma("unroll") for (int i = 0; i < 8; i++) {
            const int m = bm + ty * 8 + i;
            _Pragma("unroll") for (int j = 0; j < 8; j++) {
                const int n = bn + tx * 8 + j;
                out[(size_t)m * DIM + n] = acc[i][j] + bias[n];
            }
        }
    })
}

// ---------------------------------------------------------------------------
// Attention: one block per (b,h). K/V staged in smem; 2-pass softmax with
// recomputed scores; bias gathered through L2 (both tables L2-resident).
// ---------------------------------------------------------------------------
__global__ __launch_bounds__(128) void attn_kernel(
    const float* __restrict__ bias_table, const int* __restrict__ rel_index)
{
    __shared__ float ks[Nn * HD];
    __shared__ float vs[Nn * HD];

    const int bh = blockIdx.x;
    const int h  = bh & (NH - 1);
    const int b  = bh >> 4;

    const float* kg = g_k + (size_t)bh * Nn * HD;
    const float* vg = g_v + (size_t)bh * Nn * HD;
    for (int t = threadIdx.x; t < Nn * HD; t += 128) {
        ks[t] = kg[t];
        vs[t] = vg[t];
    }
    __syncthreads();

    const int i = threadIdx.x;
    if (i >= Nn) return;

    float qr[HD];
    const float* qp = g_q + ((size_t)bh * Nn + i) * HD;
#pragma unroll
    for (int d = 0; d < HD; d++) qr[d] = qp[d];

    const int* ri = rel_index + i * Nn;

    // pass 1: row max
    float mx = -1e30f;
    for (int j = 0; j < Nn; j++) {
        float s = 0.f;
#pragma unroll
        for (int d = 0; d < HD; d++) s += qr[d] * ks[j * HD + d];
        s += bias_table[ri[j] * NH + h];
        mx = fmaxf(mx, s);
    }

    // pass 2: exp + accumulate V
    float sum = 0.f;
    float outv[HD];
#pragma unroll
    for (int d = 0; d < HD; d++) outv[d] = 0.f;

    for (int j = 0; j < Nn; j++) {
        float s = 0.f;
#pragma unroll
        for (int d = 0; d < HD; d++) s += qr[d] * ks[j * HD + d];
        s += bias_table[ri[j] * NH + h];
        const float e = __expf(s - mx);
        sum += e;
#pragma unroll
        for (int d = 0; d < HD; d++) outv[d] += e * vs[j * HD + d];
    }

    const float inv = 1.f / sum;
    float* op = g_att + ((size_t)b * Nn + i) * DIM + h * HD;
#pragma unroll
    for (int d = 0; d < HD; d++) op[d] = outv[d] * inv;
}

// ---------------------------------------------------------------------------
// Launch
// ---------------------------------------------------------------------------
extern "C" void kernel_launch(void* const* d_in, const int* in_sizes, int n_in,
                              void* d_out, int out_size)
{
    const float* x          = (const float*)d_in[0];
    const float* qkv_w      = (const float*)d_in[1];
    const float* qkv_b      = (const float*)d_in[2];
    const float* proj_w     = (const float*)d_in[3];
    const float* proj_b     = (const float*)d_in[4];
    const float* bias_table = (const float*)d_in[5];
    const int*   rel_index  = (const int*)d_in[6];
    float*       out        = (float*)d_out;

    // fused QKV GEMM + scatter
    {
        dim3 grid(QKV_N / 128, Mrows / 128);   // (12, 392)
        qkv_gemm_kernel<<<grid, 256>>>(x, qkv_w, qkv_b);
    }
    // attention
    attn_kernel<<<BH, 128>>>(bias_table, rel_index);
    // proj GEMM (reads g_att via device symbol — pass pointer via kernel arg)
    {
        // get device pointer of g_att for the GEMM A operand
        // (device symbol address is resolvable at launch time via a tiny trampoline:
        //  simplest: use the symbol directly inside the kernel is not possible for
        //  the generic GEMM, so fetch the address host-side once per launch)
        static float* att_ptr = nullptr;
        if (!att_ptr) cudaGetSymbolAddress((void**)&att_ptr, g_att);
        dim3 grid(DIM / 128, Mrows / 128);     // (4, 392)
        proj_gemm_kernel<<<grid, 256>>>(att_ptr, proj_w, proj_b, out);
    }
}

// round 3
// speedup vs baseline: 2.2151x; 2.2151x over previous
#include <cuda_runtime.h>
#include <cuda_bf16.h>
#include <cstdint>

#define Bsz 512
#define Nn  98
#define DIM 512
#define NH  16
#define HD  32
#define Mrows (Bsz*Nn)          // 50176
#define QKV_N (3*DIM)           // 1536
#define SCALE 0.17677669529663687f
#define XELEMS ((size_t)Mrows*DIM)   // 25,690,112

#define KT 32
#define NSTAGE 3
#define TILE_B 10240            // 128 rows * 80 B
#define STAGE_B (4*TILE_B)      // 40960
#define SMEM_GEMM (NSTAGE*STAGE_B)  // 122880

// ---------------- scratch (device globals; allocation-free rule) ------------
__device__ float g_q[(size_t)Bsz*NH*Nn*HD];
__device__ float g_k[(size_t)Bsz*NH*Nn*HD];
__device__ float g_v[(size_t)Bsz*NH*Nn*HD];
__device__ __nv_bfloat16 g_xh[XELEMS];
__device__ __nv_bfloat16 g_xl[XELEMS];
__device__ __nv_bfloat16 g_ah[XELEMS];
__device__ __nv_bfloat16 g_al[XELEMS];
__device__ __nv_bfloat16 g_wqh[(size_t)QKV_N*DIM];
__device__ __nv_bfloat16 g_wql[(size_t)QKV_N*DIM];
__device__ __nv_bfloat16 g_wph[(size_t)DIM*DIM];
__device__ __nv_bfloat16 g_wpl[(size_t)DIM*DIM];
__device__ float g_bias_pre[NH*Nn*Nn];

// ---------------- helpers ----------------------------------------------------
__device__ __forceinline__ uint32_t smem_u32(const void* p) {
    uint32_t a;
    asm("{ .reg .u64 t; cvta.to.shared.u64 t, %1; cvt.u32.u64 %0, t; }"
        : "=r"(a) : "l"(p));
    return a;
}
__device__ __forceinline__ void cp16(uint32_t s, const void* g) {
    asm volatile("cp.async.cg.shared.global [%0], [%1], 16;" :: "r"(s), "l"(g));
}
__device__ __forceinline__ void ldsm4(uint32_t& r0, uint32_t& r1, uint32_t& r2,
                                      uint32_t& r3, uint32_t a) {
    asm volatile("ldmatrix.sync.aligned.m8n8.x4.shared.b16 {%0,%1,%2,%3}, [%4];"
                 : "=r"(r0), "=r"(r1), "=r"(r2), "=r"(r3) : "r"(a));
}
__device__ __forceinline__ void mma4(float* d, const uint32_t* a, const uint32_t* b) {
    asm volatile("mma.sync.aligned.m16n8k16.row.col.f32.bf16.bf16.f32 "
                 "{%0,%1,%2,%3}, {%4,%5,%6,%7}, {%8,%9}, {%0,%1,%2,%3};"
                 : "+f"(d[0]), "+f"(d[1]), "+f"(d[2]), "+f"(d[3])
                 : "r"(a[0]), "r"(a[1]), "r"(a[2]), "r"(a[3]), "r"(b[0]), "r"(b[1]));
}
__device__ __forceinline__ uint32_t packbf2(__nv_bfloat16 a, __nv_bfloat16 b) {
    __nv_bfloat162 t = __halves2bfloat162(a, b);
    return reinterpret_cast<uint32_t&>(t);
}

// ---------------- conversion kernels ----------------------------------------
__global__ __launch_bounds__(256) void conv_x_kernel(const float* __restrict__ x) {
    size_t i = (size_t)blockIdx.x * 256 + threadIdx.x;
    if (i >= XELEMS / 4) return;
    float4 v = ((const float4*)x)[i];
    __nv_bfloat16 h0 = __float2bfloat16(v.x), h1 = __float2bfloat16(v.y);
    __nv_bfloat16 h2 = __float2bfloat16(v.z), h3 = __float2bfloat16(v.w);
    __nv_bfloat16 l0 = __float2bfloat16(v.x - __bfloat162float(h0));
    __nv_bfloat16 l1 = __float2bfloat16(v.y - __bfloat162float(h1));
    __nv_bfloat16 l2 = __float2bfloat16(v.z - __bfloat162float(h2));
    __nv_bfloat16 l3 = __float2bfloat16(v.w - __bfloat162float(h3));
    ((uint2*)g_xh)[i] = make_uint2(packbf2(h0, h1), packbf2(h2, h3));
    ((uint2*)g_xl)[i] = make_uint2(packbf2(l0, l1), packbf2(l2, l3));
}
__global__ __launch_bounds__(256) void transw_qkv_kernel(const float* __restrict__ w) {
    int idx = blockIdx.x * 256 + threadIdx.x;
    if (idx >= QKV_N * DIM) return;
    int n = idx >> 9, k = idx & 511;
    float v = w[(size_t)k * QKV_N + n];
    __nv_bfloat16 h = __float2bfloat16(v);
    g_wqh[idx] = h;
    g_wql[idx] = __float2bfloat16(v - __bfloat162float(h));
}
__global__ __launch_bounds__(256) void transw_proj_kernel(const float* __restrict__ w) {
    int idx = blockIdx.x * 256 + threadIdx.x;
    if (idx >= DIM * DIM) return;
    int n = idx >> 9, k = idx & 511;
    float v = w[(size_t)k * DIM + n];
    __nv_bfloat16 h = __float2bfloat16(v);
    g_wph[idx] = h;
    g_wpl[idx] = __float2bfloat16(v - __bfloat162float(h));
}
__global__ __launch_bounds__(256) void bias_pre_kernel(const float* __restrict__ bt,
                                                       const int* __restrict__ ri) {
    int idx = blockIdx.x * 256 + threadIdx.x;
    if (idx >= NH * Nn * Nn) return;
    int h = idx / (Nn * Nn);
    int t = idx - h * (Nn * Nn);
    g_bias_pre[idx] = bt[ri[t] * NH + h];
}

// ---------------- HMMA GEMM: 128x128 tile, hi/lo bf16 split (3 passes) ------
// A: [M,512] bf16 hi/lo row-major; B: [N,512] bf16 hi/lo (pre-transposed).
template<bool IS_QKV>
__global__ __launch_bounds__(256) void gemm_kernel(const float* __restrict__ bias,
                                                   float* __restrict__ outp) {
    extern __shared__ __align__(16) char smraw[];
    const uint32_t sbase = smem_u32(smraw);
    const int tid = threadIdx.x;
    const int wid = tid >> 5, l = tid & 31;
    const int bm = blockIdx.y * 128, bn = blockIdx.x * 128;
    const int wm = wid & 1, wn = wid >> 1;   // warp tile: 64(M) x 32(N)

    const __nv_bfloat16* __restrict__ Ah = IS_QKV ? g_xh : g_ah;
    const __nv_bfloat16* __restrict__ Al = IS_QKV ? g_xl : g_al;
    const __nv_bfloat16* __restrict__ Bh = IS_QKV ? g_wqh : g_wph;
    const __nv_bfloat16* __restrict__ Bl = IS_QKV ? g_wql : g_wpl;

    auto issue = [&](int st, int kt) {
        const int k0 = kt * KT;
        const uint32_t base = sbase + st * STAGE_B;
#pragma unroll
        for (int i = 0; i < 2; i++) {
            int o = tid + 256 * i;
            int row = o >> 2, c = o & 3;
            uint32_t so = row * 80 + c * 16;
            size_t ga = (size_t)(bm + row) * 512 + k0 + c * 8;
            size_t gb = (size_t)(bn + row) * 512 + k0 + c * 8;
            cp16(base + so,             Ah + ga);
            cp16(base + TILE_B + so,    Al + ga);
            cp16(base + 2*TILE_B + so,  Bh + gb);
            cp16(base + 3*TILE_B + so,  Bl + gb);
        }
        asm volatile("cp.async.commit_group;" ::: "memory");
    };

    float acc[4][4][4];
#pragma unroll
    for (int a = 0; a < 4; a++)
#pragma unroll
        for (int b = 0; b < 4; b++)
#pragma unroll
            for (int c = 0; c < 4; c++) acc[a][b][c] = 0.f;

    issue(0, 0);
    issue(1, 1);

    for (int kt = 0; kt < 16; kt++) {
        if (kt < 15) asm volatile("cp.async.wait_group 1;" ::: "memory");
        else         asm volatile("cp.async.wait_group 0;" ::: "memory");
        __syncthreads();
        if (kt + 2 < 16) issue((kt + 2) % NSTAGE, kt + 2);

        const uint32_t base = sbase + (kt % NSTAGE) * STAGE_B;
#pragma unroll
        for (int ks = 0; ks < 2; ks++) {
            uint32_t ahf[4][4], alf[4][4], bhf[4][2], blf[4][2];
#pragma unroll
            for (int mi = 0; mi < 4; mi++) {
                uint32_t ad = base + (uint32_t)(wm * 64 + mi * 16 + (l & 15)) * 80
                            + (uint32_t)(ks * 2 + (l >> 4)) * 16;
                ldsm4(ahf[mi][0], ahf[mi][1], ahf[mi][2], ahf[mi][3], ad);
                ldsm4(alf[mi][0], alf[mi][1], alf[mi][2], alf[mi][3], ad + TILE_B);
            }
#pragma unroll
            for (int p = 0; p < 2; p++) {
                uint32_t nrow = (uint32_t)(wn * 32 + p * 16 + (l >> 4) * 8 + (l & 7));
                uint32_t ck   = (uint32_t)(ks * 2 + ((l >> 3) & 1));
                uint32_t bd = base + 2 * TILE_B + nrow * 80 + ck * 16;
                uint32_t r0, r1, r2, r3;
                ldsm4(r0, r1, r2, r3, bd);
                bhf[2*p][0] = r0; bhf[2*p][1] = r1; bhf[2*p+1][0] = r2; bhf[2*p+1][1] = r3;
                ldsm4(r0, r1, r2, r3, bd + TILE_B);
                blf[2*p][0] = r0; blf[2*p][1] = r1; blf[2*p+1][0] = r2; blf[2*p+1][1] = r3;
            }
#pragma unroll
            for (int mi = 0; mi < 4; mi++)
#pragma unroll
                for (int ni = 0; ni < 4; ni++) {
                    mma4(acc[mi][ni], ahf[mi], bhf[ni]);
                    mma4(acc[mi][ni], ahf[mi], blf[ni]);
                    mma4(acc[mi][ni], alf[mi], bhf[ni]);
                }
        }
    }

    // -------- epilogue straight from accumulators --------
    if (IS_QKV) {
        const int which = bn >> 9;                 // tile never crosses q/k/v split
        const int h = ((bn >> 5) + wn) & (NH - 1); // warp tile = one head
        float* dst0 = which == 0 ? g_q : which == 1 ? g_k : g_v;
        const float sc = which == 0 ? SCALE : 1.f;
        const float* bptr = bias + which * 512 + h * 32;
#pragma unroll
        for (int mi = 0; mi < 4; mi++) {
#pragma unroll
            for (int rr = 0; rr < 2; rr++) {
                int m = bm + wm * 64 + mi * 16 + (l >> 2) + rr * 8;
                int b = m / Nn, r = m - b * Nn;
                float* rowp = dst0 + ((size_t)(b * NH + h) * Nn + r) * HD;
#pragma unroll
                for (int ni = 0; ni < 4; ni++) {
                    int hd = ni * 8 + 2 * (l & 3);
                    float v0 = (acc[mi][ni][rr * 2 + 0] + bptr[hd])     * sc;
                    float v1 = (acc[mi][ni][rr * 2 + 1] + bptr[hd + 1]) * sc;
                    *(float2*)(rowp + hd) = make_float2(v0, v1);
                }
            }
        }
    } else {
        const int nb = bn + wn * 32;
#pragma unroll
        for (int mi = 0; mi < 4; mi++) {
#pragma unroll
            for (int rr = 0; rr < 2; rr++) {
                int m = bm + wm * 64 + mi * 16 + (l >> 2) + rr * 8;
                float* rowp = outp + (size_t)m * DIM + nb;
#pragma unroll
                for (int ni = 0; ni < 4; ni++) {
                    int off = ni * 8 + 2 * (l & 3);
                    float v0 = acc[mi][ni][rr * 2 + 0] + bias[nb + off];
                    float v1 = acc[mi][ni][rr * 2 + 1] + bias[nb + off + 1];
                    *(float2*)(rowp + off) = make_float2(v0, v1);
                }
            }
        }
    }
}

// ---------------- attention --------------------------------------------------
__global__ __launch_bounds__(128) void attn_kernel() {
    extern __shared__ float sm[];
    float* ks = sm;              // 3136
    float* vs = sm + 3136;       // 3136
    float* sc = sm + 6272;       // 98*99

    const int bh = blockIdx.x;
    const int h = bh & (NH - 1);
    const int b = bh >> 4;

    const float4* kg = (const float4*)(g_k + (size_t)bh * Nn * HD);
    const float4* vg = (const float4*)(g_v + (size_t)bh * Nn * HD);
    for (int t = threadIdx.x; t < Nn * HD / 4; t += 128) {
        ((float4*)ks)[t] = kg[t];
        ((float4*)vs)[t] = vg[t];
    }
    const float* bp = g_bias_pre + h * (Nn * Nn);
    for (int t = threadIdx.x; t < Nn * Nn; t += 128) {
        int i = t / Nn;
        int j = t - i * Nn;
        sc[i * 99 + j] = bp[t];
    }
    __syncthreads();

    const int i = threadIdx.x;
    if (i < Nn) {
        float qr[HD];
        const float4* qp = (const float4*)(g_q + ((size_t)bh * Nn + i) * HD);
#pragma unroll
        for (int d4 = 0; d4 < 8; d4++) {
            float4 v = qp[d4];
            qr[4*d4] = v.x; qr[4*d4+1] = v.y; qr[4*d4+2] = v.z; qr[4*d4+3] = v.w;
        }
        float mx = -1e30f;
        for (int j = 0; j < Nn; j++) {
            const float4* kr = (const float4*)(ks + j * HD);
            float s = sc[i * 99 + j];
#pragma unroll
            for (int d4 = 0; d4 < 8; d4++) {
                float4 kv = kr[d4];
                s += qr[4*d4] * kv.x + qr[4*d4+1] * kv.y
                   + qr[4*d4+2] * kv.z + qr[4*d4+3] * kv.w;
            }
            sc[i * 99 + j] = s;
            mx = fmaxf(mx, s);
        }
        float sum = 0.f;
        float outv[HD];
#pragma unroll
        for (int d = 0; d < HD; d++) outv[d] = 0.f;
        for (int j = 0; j < Nn; j++) {
            const float e = __expf(sc[i * 99 + j] - mx);
            sum += e;
            const float4* vr = (const float4*)(vs + j * HD);
#pragma unroll
            for (int d4 = 0; d4 < 8; d4++) {
                float4 vv = vr[d4];
                outv[4*d4]   += e * vv.x;
                outv[4*d4+1] += e * vv.y;
                outv[4*d4+2] += e * vv.z;
                outv[4*d4+3] += e * vv.w;
            }
        }
        const float inv = 1.f / sum;

        const size_t off = ((size_t)b * Nn + i) * DIM + h * HD;
        uint32_t hp[16], lp[16];
#pragma unroll
        for (int d2 = 0; d2 < 16; d2++) {
            float a = outv[2*d2] * inv;
            float c = outv[2*d2+1] * inv;
            __nv_bfloat16 ha = __float2bfloat16(a);
            __nv_bfloat16 hc = __float2bfloat16(c);
            hp[d2] = packbf2(ha, hc);
            lp[d2] = packbf2(__float2bfloat16(a - __bfloat162float(ha)),
                             __float2bfloat16(c - __bfloat162float(hc)));
        }
        uint4* gh = (uint4*)(g_ah + off);
        uint4* gl = (uint4*)(g_al + off);
#pragma unroll
        for (int t = 0; t < 4; t++) {
            gh[t] = make_uint4(hp[4*t], hp[4*t+1], hp[4*t+2], hp[4*t+3]);
            gl[t] = make_uint4(lp[4*t], lp[4*t+1], lp[4*t+2], lp[4*t+3]);
        }
    }
}

// ---------------- launch -----------------------------------------------------
extern "C" void kernel_launch(void* const* d_in, const int* in_sizes, int n_in,
                              void* d_out, int out_size) {
    const float* x          = (const float*)d_in[0];
    const float* qkv_w      = (const float*)d_in[1];
    const float* qkv_b      = (const float*)d_in[2];
    const float* proj_w     = (const float*)d_in[3];
    const float* proj_b     = (const float*)d_in[4];
    const float* bias_table = (const float*)d_in[5];
    const int*   rel_index  = (const int*)d_in[6];
    float*       out        = (float*)d_out;

    static bool inited = false;
    if (!inited) {
        cudaFuncSetAttribute(gemm_kernel<true>,
                             cudaFuncAttributeMaxDynamicSharedMemorySize, SMEM_GEMM);
        cudaFuncSetAttribute(gemm_kernel<false>,
                             cudaFuncAttributeMaxDynamicSharedMemorySize, SMEM_GEMM);
        cudaFuncSetAttribute(attn_kernel,
                             cudaFuncAttributeMaxDynamicSharedMemorySize, 64000);
        inited = true;
    }

    conv_x_kernel<<<(int)((XELEMS / 4 + 255) / 256), 256>>>(x);
    transw_qkv_kernel<<<(QKV_N * DIM + 255) / 256, 256>>>(qkv_w);
    transw_proj_kernel<<<(DIM * DIM + 255) / 256, 256>>>(proj_w);
    bias_pre_kernel<<<(NH * Nn * Nn + 255) / 256, 256>>>(bias_table, rel_index);

    gemm_kernel<true><<<dim3(QKV_N / 128, Mrows / 128), 256, SMEM_GEMM>>>(qkv_b, nullptr);
    attn_kernel<<<Bsz * NH, 128, 64000>>>();
    gemm_kernel<false><<<dim3(DIM / 128, Mrows / 128), 256, SMEM_GEMM>>>(proj_b, out);
}

// round 4
// speedup vs baseline: 3.0513x; 1.3775x over previous
#include <cuda_runtime.h>
#include <cuda_fp16.h>
#include <cstdint>

#define Bsz 512
#define Nn  98
#define DIM 512
#define NH  16
#define HD  32
#define Mrows (Bsz*Nn)          // 50176
#define QKV_N (3*DIM)           // 1536
#define SCALE 0.17677669529663687f
#define XELEMS ((size_t)Mrows*DIM)   // 25,690,112

#define KT 32
#define NSTAGE 3
#define TILE_B 10240            // 128 rows * 80 B
#define STAGE_B (3*TILE_B)      // 30720 (A_hi, B_hi, B_lo)
#define SMEM_GEMM (NSTAGE*STAGE_B)  // 92160

// ---------------- scratch (device globals; allocation-free rule) ------------
__device__ float g_q[(size_t)Bsz*NH*Nn*HD];
__device__ float g_k[(size_t)Bsz*NH*Nn*HD];
__device__ float g_v[(size_t)Bsz*NH*Nn*HD];
__device__ __half g_xh[XELEMS];           // x rounded to fp16
__device__ __half g_ah[XELEMS];           // attn output rounded to fp16
__device__ __half g_wqh[(size_t)QKV_N*DIM];
__device__ __half g_wql[(size_t)QKV_N*DIM];
__device__ __half g_wph[(size_t)DIM*DIM];
__device__ __half g_wpl[(size_t)DIM*DIM];
__device__ float g_bias_pre[NH*Nn*Nn];

// ---------------- helpers ----------------------------------------------------
__device__ __forceinline__ uint32_t smem_u32(const void* p) {
    uint32_t a;
    asm("{ .reg .u64 t; cvta.to.shared.u64 t, %1; cvt.u32.u64 %0, t; }"
        : "=r"(a) : "l"(p));
    return a;
}
__device__ __forceinline__ void cp16(uint32_t s, const void* g) {
    asm volatile("cp.async.cg.shared.global [%0], [%1], 16;" :: "r"(s), "l"(g));
}
__device__ __forceinline__ void ldsm4(uint32_t& r0, uint32_t& r1, uint32_t& r2,
                                      uint32_t& r3, uint32_t a) {
    asm volatile("ldmatrix.sync.aligned.m8n8.x4.shared.b16 {%0,%1,%2,%3}, [%4];"
                 : "=r"(r0), "=r"(r1), "=r"(r2), "=r"(r3) : "r"(a));
}
__device__ __forceinline__ void mma4(float* d, const uint32_t* a, const uint32_t* b) {
    asm volatile("mma.sync.aligned.m16n8k16.row.col.f32.f16.f16.f32 "
                 "{%0,%1,%2,%3}, {%4,%5,%6,%7}, {%8,%9}, {%0,%1,%2,%3};"
                 : "+f"(d[0]), "+f"(d[1]), "+f"(d[2]), "+f"(d[3])
                 : "r"(a[0]), "r"(a[1]), "r"(a[2]), "r"(a[3]), "r"(b[0]), "r"(b[1]));
}
__device__ __forceinline__ uint32_t packh2(__half a, __half b) {
    __half2 t = __halves2half2(a, b);
    return reinterpret_cast<uint32_t&>(t);
}

// ---------------- conversion kernels ----------------------------------------
__global__ __launch_bounds__(256) void conv_x_kernel(const float* __restrict__ x) {
    size_t i = (size_t)blockIdx.x * 256 + threadIdx.x;
    if (i >= XELEMS / 4) return;
    float4 v = ((const float4*)x)[i];
    ((uint2*)g_xh)[i] = make_uint2(
        packh2(__float2half(v.x), __float2half(v.y)),
        packh2(__float2half(v.z), __float2half(v.w)));
}
__global__ __launch_bounds__(256) void transw_qkv_kernel(const float* __restrict__ w) {
    int idx = blockIdx.x * 256 + threadIdx.x;
    if (idx >= QKV_N * DIM) return;
    int n = idx >> 9, k = idx & 511;
    float v = w[(size_t)k * QKV_N + n];
    __half h = __float2half(v);
    g_wqh[idx] = h;
    g_wql[idx] = __float2half(v - __half2float(h));
}
__global__ __launch_bounds__(256) void transw_proj_kernel(const float* __restrict__ w) {
    int idx = blockIdx.x * 256 + threadIdx.x;
    if (idx >= DIM * DIM) return;
    int n = idx >> 9, k = idx & 511;
    float v = w[(size_t)k * DIM + n];
    __half h = __float2half(v);
    g_wph[idx] = h;
    g_wpl[idx] = __float2half(v - __half2float(h));
}
__global__ __launch_bounds__(256) void bias_pre_kernel(const float* __restrict__ bt,
                                                       const int* __restrict__ ri) {
    int idx = blockIdx.x * 256 + threadIdx.x;
    if (idx >= NH * Nn * Nn) return;
    int h = idx / (Nn * Nn);
    int t = idx - h * (Nn * Nn);
    g_bias_pre[idx] = bt[ri[t] * NH + h];
}

// ---------------- HMMA GEMM: 128x128 tile, fp16, D = A_hi*(B_hi + B_lo) -----
// A: [M,512] fp16 row-major; B: [N,512] fp16 hi/lo (pre-transposed weights).
template<bool IS_QKV>
__global__ __launch_bounds__(256) void gemm_kernel(const float* __restrict__ bias,
                                                   float* __restrict__ outp) {
    extern __shared__ __align__(16) char smraw[];
    const uint32_t sbase = smem_u32(smraw);
    const int tid = threadIdx.x;
    const int wid = tid >> 5, l = tid & 31;
    const int bm = blockIdx.y * 128, bn = blockIdx.x * 128;
    const int wm = wid & 1, wn = wid >> 1;   // warp tile: 64(M) x 32(N)

    const __half* __restrict__ Ah = IS_QKV ? g_xh : g_ah;
    const __half* __restrict__ Bh = IS_QKV ? g_wqh : g_wph;
    const __half* __restrict__ Bl = IS_QKV ? g_wql : g_wpl;

    auto issue = [&](int st, int kt) {
        const int k0 = kt * KT;
        const uint32_t base = sbase + st * STAGE_B;
        const int c = tid & 3;
#pragma unroll
        for (int i = 0; i < 6; i++) {
            const int tile = i >> 1;
            const int row = ((i & 1) * 256 + tid) >> 2;
            uint32_t so = base + tile * TILE_B + row * 80 + c * 16;
            if (tile == 0)
                cp16(so, Ah + (size_t)(bm + row) * 512 + k0 + c * 8);
            else if (tile == 1)
                cp16(so, Bh + (size_t)(bn + row) * 512 + k0 + c * 8);
            else
                cp16(so, Bl + (size_t)(bn + row) * 512 + k0 + c * 8);
        }
        asm volatile("cp.async.commit_group;" ::: "memory");
    };

    float acc[4][4][4];
#pragma unroll
    for (int a = 0; a < 4; a++)
#pragma unroll
        for (int b = 0; b < 4; b++)
#pragma unroll
            for (int c = 0; c < 4; c++) acc[a][b][c] = 0.f;

    issue(0, 0);
    issue(1, 1);

    for (int kt = 0; kt < 16; kt++) {
        if (kt < 15) asm volatile("cp.async.wait_group 1;" ::: "memory");
        else         asm volatile("cp.async.wait_group 0;" ::: "memory");
        __syncthreads();
        if (kt + 2 < 16) issue((kt + 2) % NSTAGE, kt + 2);

        const uint32_t base = sbase + (kt % NSTAGE) * STAGE_B;
#pragma unroll
        for (int ks = 0; ks < 2; ks++) {
            uint32_t af[4][4], bhf[4][2], blf[4][2];
#pragma unroll
            for (int mi = 0; mi < 4; mi++) {
                uint32_t ad = base + (uint32_t)(wm * 64 + mi * 16 + (l & 15)) * 80
                            + (uint32_t)(ks * 2 + (l >> 4)) * 16;
                ldsm4(af[mi][0], af[mi][1], af[mi][2], af[mi][3], ad);
            }
#pragma unroll
            for (int p = 0; p < 2; p++) {
                uint32_t nrow = (uint32_t)(wn * 32 + p * 16 + (l >> 4) * 8 + (l & 7));
                uint32_t ck   = (uint32_t)(ks * 2 + ((l >> 3) & 1));
                uint32_t bd = base + TILE_B + nrow * 80 + ck * 16;
                uint32_t r0, r1, r2, r3;
                ldsm4(r0, r1, r2, r3, bd);
                bhf[2*p][0] = r0; bhf[2*p][1] = r1; bhf[2*p+1][0] = r2; bhf[2*p+1][1] = r3;
                ldsm4(r0, r1, r2, r3, bd + TILE_B);
                blf[2*p][0] = r0; blf[2*p][1] = r1; blf[2*p+1][0] = r2; blf[2*p+1][1] = r3;
            }
#pragma unroll
            for (int mi = 0; mi < 4; mi++)
#pragma unroll
                for (int ni = 0; ni < 4; ni++) {
                    mma4(acc[mi][ni], af[mi], bhf[ni]);
                    mma4(acc[mi][ni], af[mi], blf[ni]);
                }
        }
    }

    // -------- epilogue straight from accumulators --------
    if (IS_QKV) {
        const int which = bn >> 9;                 // tile never crosses q/k/v split
        const int h = ((bn >> 5) + wn) & (NH - 1); // warp tile = one head
        float* dst0 = which == 0 ? g_q : which == 1 ? g_k : g_v;
        const float sc = which == 0 ? SCALE : 1.f;
        const float* bptr = bias + which * 512 + h * 32;
#pragma unroll
        for (int mi = 0; mi < 4; mi++) {
#pragma unroll
            for (int rr = 0; rr < 2; rr++) {
                int m = bm + wm * 64 + mi * 16 + (l >> 2) + rr * 8;
                int b = m / Nn, r = m - b * Nn;
                float* rowp = dst0 + ((size_t)(b * NH + h) * Nn + r) * HD;
#pragma unroll
                for (int ni = 0; ni < 4; ni++) {
                    int hd = ni * 8 + 2 * (l & 3);
                    float v0 = (acc[mi][ni][rr * 2 + 0] + bptr[hd])     * sc;
                    float v1 = (acc[mi][ni][rr * 2 + 1] + bptr[hd + 1]) * sc;
                    *(float2*)(rowp + hd) = make_float2(v0, v1);
                }
            }
        }
    } else {
        const int nb = bn + wn * 32;
#pragma unroll
        for (int mi = 0; mi < 4; mi++) {
#pragma unroll
            for (int rr = 0; rr < 2; rr++) {
                int m = bm + wm * 64 + mi * 16 + (l >> 2) + rr * 8;
                float* rowp = outp + (size_t)m * DIM + nb;
#pragma unroll
                for (int ni = 0; ni < 4; ni++) {
                    int off = ni * 8 + 2 * (l & 3);
                    float v0 = acc[mi][ni][rr * 2 + 0] + bias[nb + off];
                    float v1 = acc[mi][ni][rr * 2 + 1] + bias[nb + off + 1];
                    *(float2*)(rowp + off) = make_float2(v0, v1);
                }
            }
        }
    }
}

// ---------------- attention --------------------------------------------------
__global__ __launch_bounds__(128) void attn_kernel() {
    extern __shared__ float sm[];
    float* ks = sm;              // 3136
    float* vs = sm + 3136;       // 3136
    float* sc = sm + 6272;       // 98*99

    const int bh = blockIdx.x;
    const int h = bh & (NH - 1);
    const int b = bh >> 4;

    const float4* kg = (const float4*)(g_k + (size_t)bh * Nn * HD);
    const float4* vg = (const float4*)(g_v + (size_t)bh * Nn * HD);
    for (int t = threadIdx.x; t < Nn * HD / 4; t += 128) {
        ((float4*)ks)[t] = kg[t];
        ((float4*)vs)[t] = vg[t];
    }
    const float* bp = g_bias_pre + h * (Nn * Nn);
    for (int t = threadIdx.x; t < Nn * Nn; t += 128) {
        int i = t / Nn;
        int j = t - i * Nn;
        sc[i * 99 + j] = bp[t];
    }
    __syncthreads();

    const int i = threadIdx.x;
    if (i < Nn) {
        float qr[HD];
        const float4* qp = (const float4*)(g_q + ((size_t)bh * Nn + i) * HD);
#pragma unroll
        for (int d4 = 0; d4 < 8; d4++) {
            float4 v = qp[d4];
            qr[4*d4] = v.x; qr[4*d4+1] = v.y; qr[4*d4+2] = v.z; qr[4*d4+3] = v.w;
        }
        float mx = -1e30f;
        for (int j = 0; j < Nn; j++) {
            const float4* kr = (const float4*)(ks + j * HD);
            float s0 = 0.f, s1 = 0.f, s2 = 0.f, s3 = 0.f;
#pragma unroll
            for (int d4 = 0; d4 < 8; d4++) {
                float4 kv = kr[d4];
                s0 += qr[4*d4]   * kv.x;
                s1 += qr[4*d4+1] * kv.y;
                s2 += qr[4*d4+2] * kv.z;
                s3 += qr[4*d4+3] * kv.w;
            }
            float s = sc[i * 99 + j] + ((s0 + s1) + (s2 + s3));
            sc[i * 99 + j] = s;
            mx = fmaxf(mx, s);
        }
        float sum = 0.f;
        float outv[HD];
#pragma unroll
        for (int d = 0; d < HD; d++) outv[d] = 0.f;
        for (int j = 0; j < Nn; j++) {
            const float e = __expf(sc[i * 99 + j] - mx);
            sum += e;
            const float4* vr = (const float4*)(vs + j * HD);
#pragma unroll
            for (int d4 = 0; d4 < 8; d4++) {
                float4 vv = vr[d4];
                outv[4*d4]   += e * vv.x;
                outv[4*d4+1] += e * vv.y;
                outv[4*d4+2] += e * vv.z;
                outv[4*d4+3] += e * vv.w;
            }
        }
        const float inv = 1.f / sum;

        // write fp16 for the proj GEMM input, layout [Mrows, DIM]
        const size_t off = ((size_t)b * Nn + i) * DIM + h * HD;
        uint32_t hp[16];
#pragma unroll
        for (int d2 = 0; d2 < 16; d2++)
            hp[d2] = packh2(__float2half(outv[2*d2] * inv),
                            __float2half(outv[2*d2+1] * inv));
        uint4* gh = (uint4*)(g_ah + off);
#pragma unroll
        for (int t = 0; t < 4; t++)
            gh[t] = make_uint4(hp[4*t], hp[4*t+1], hp[4*t+2], hp[4*t+3]);
    }
}

// ---------------- launch -----------------------------------------------------
extern "C" void kernel_launch(void* const* d_in, const int* in_sizes, int n_in,
                              void* d_out, int out_size) {
    const float* x          = (const float*)d_in[0];
    const float* qkv_w      = (const float*)d_in[1];
    const float* qkv_b      = (const float*)d_in[2];
    const float* proj_w     = (const float*)d_in[3];
    const float* proj_b     = (const float*)d_in[4];
    const float* bias_table = (const float*)d_in[5];
    const int*   rel_index  = (const int*)d_in[6];
    float*       out        = (float*)d_out;

    static bool inited = false;
    if (!inited) {
        cudaFuncSetAttribute(gemm_kernel<true>,
                             cudaFuncAttributeMaxDynamicSharedMemorySize, SMEM_GEMM);
        cudaFuncSetAttribute(gemm_kernel<false>,
                             cudaFuncAttributeMaxDynamicSharedMemorySize, SMEM_GEMM);
        cudaFuncSetAttribute(attn_kernel,
                             cudaFuncAttributeMaxDynamicSharedMemorySize, 64000);
        inited = true;
    }

    conv_x_kernel<<<(int)((XELEMS / 4 + 255) / 256), 256>>>(x);
    transw_qkv_kernel<<<(QKV_N * DIM + 255) / 256, 256>>>(qkv_w);
    transw_proj_kernel<<<(DIM * DIM + 255) / 256, 256>>>(proj_w);
    bias_pre_kernel<<<(NH * Nn * Nn + 255) / 256, 256>>>(bias_table, rel_index);

    gemm_kernel<true><<<dim3(QKV_N / 128, Mrows / 128), 256, SMEM_GEMM>>>(qkv_b, nullptr);
    attn_kernel<<<Bsz * NH, 128, 64000>>>();
    gemm_kernel<false><<<dim3(DIM / 128, Mrows / 128), 256, SMEM_GEMM>>>(proj_b, out);
}